// round 17
// baseline (speedup 1.0000x reference)
#include <cuda_runtime.h>
#include <cuda_fp16.h>
#include <math.h>
#include <stdint.h>

#define NN 50000
#define HD 128
#define EE 600000
#define SCAN_BLOCKS ((NN + 255) / 256)   // 196
#define MB_TILES ((NN + 127) / 128)      // 391
#define PH 136                            // smem pitch in halves (272 B, 16-aligned)
#define GEMM_SMEM (2 * 128 * PH * 2)      // 69632 B (A-hi + W)

// Scratch (device globals — no allocation allowed in kernel_launch)
__device__ __align__(16) __half g_xwh[NN * HD];     // fp16 XW (gather consumer)
__device__ __align__(16) __half g_wth[4 * HD * HD]; // fp16 transposed W [l][n][k]
__device__ float g_h1 [NN * HD];
__device__ float g_h2 [NN * HD];
__device__ float g_dinv[NN];
__device__ int   g_deg [NN];
__device__ int   g_rowptr[NN + 1];
__device__ int   g_head[NN];
__device__ int   g_bsum[SCAN_BLOCKS];
__device__ int   g_boff[SCAN_BLOCKS];
__device__ unsigned long long g_csr[EE];   // [w:f32 | src:i32]

__device__ __forceinline__ float elu(float v) {
    return v > 0.f ? v : expm1f(v);
}

union H4U { uint2 u; __half2 h[2]; };

__device__ __forceinline__ void mma_f16(float* d,
    uint32_t a0, uint32_t a1, uint32_t a2, uint32_t a3,
    uint32_t b0, uint32_t b1) {
    asm volatile(
        "mma.sync.aligned.m16n8k16.row.col.f32.f16.f16.f32 "
        "{%0,%1,%2,%3}, {%4,%5,%6,%7}, {%8,%9}, {%0,%1,%2,%3};"
        : "+f"(d[0]), "+f"(d[1]), "+f"(d[2]), "+f"(d[3])
        : "r"(a0), "r"(a1), "r"(a2), "r"(a3), "r"(b0), "r"(b1));
}

__device__ __forceinline__ uint32_t smem_u32(const void* p) {
    uint32_t a;
    asm("{ .reg .u64 t; cvta.to.shared.u64 t, %1; cvt.u32.u64 %0, t; }"
        : "=r"(a) : "l"(p));
    return a;
}

__device__ __forceinline__ void ldsm_x4(uint32_t& r0, uint32_t& r1,
                                        uint32_t& r2, uint32_t& r3,
                                        uint32_t addr) {
    asm volatile("ldmatrix.sync.aligned.m8n8.x4.shared.b16 {%0,%1,%2,%3}, [%4];"
                 : "=r"(r0), "=r"(r1), "=r"(r2), "=r"(r3) : "r"(addr));
}

// ---------------------------------------------------------------------------
// Degree / normalization / CSR build
// ---------------------------------------------------------------------------
__global__ void k_zero_deg(int* __restrict__ deg) {
    int i = blockIdx.x * blockDim.x + threadIdx.x;
    if (i < NN) deg[i] = 0;
}

__global__ void k_hist(const int* __restrict__ dst, int* __restrict__ deg) {
    int i = blockIdx.x * blockDim.x + threadIdx.x;
    if (i < EE) atomicAdd(&deg[dst[i]], 1);
}

__global__ void k_blockred(const int* __restrict__ deg, float* __restrict__ dinv) {
    __shared__ int wsum[8];
    int tid = threadIdx.x;
    int i = blockIdx.x * 256 + tid;
    int v = (i < NN) ? deg[i] : 0;
    if (i < NN) dinv[i] = rsqrtf((float)v + 1.0f);

    int x = v;
    #pragma unroll
    for (int off = 16; off; off >>= 1)
        x += __shfl_down_sync(0xffffffffu, x, off);
    if ((tid & 31) == 0) wsum[tid >> 5] = x;
    __syncthreads();
    if (tid < 8) {
        int s = wsum[tid];
        #pragma unroll
        for (int off = 4; off; off >>= 1)
            s += __shfl_down_sync(0xffu, s, off);
        if (tid == 0) g_bsum[blockIdx.x] = s;
    }
}

__global__ void k_scansums() {
    __shared__ int wsum[8];
    int tid = threadIdx.x;
    int lane = tid & 31, wid = tid >> 5;
    int v = (tid < SCAN_BLOCKS) ? g_bsum[tid] : 0;
    int x = v;
    #pragma unroll
    for (int off = 1; off < 32; off <<= 1) {
        int y = __shfl_up_sync(0xffffffffu, x, off);
        if (lane >= off) x += y;
    }
    if (lane == 31) wsum[wid] = x;
    __syncthreads();
    if (wid == 0 && lane < 8) {
        int s = wsum[lane];
        #pragma unroll
        for (int off = 1; off < 8; off <<= 1) {
            int y = __shfl_up_sync(0xffu, s, off);
            if (lane >= off) s += y;
        }
        wsum[lane] = s;
    }
    __syncthreads();
    int excl = x - v + (wid ? wsum[wid - 1] : 0);
    if (tid < SCAN_BLOCKS) g_boff[tid] = excl;
    if (tid == SCAN_BLOCKS - 1) g_rowptr[NN] = excl + v;
}

__global__ void k_scanfinal(const int* __restrict__ deg) {
    __shared__ int wsum[8];
    int tid = threadIdx.x;
    int lane = tid & 31, wid = tid >> 5;
    int i = blockIdx.x * 256 + tid;
    int v = (i < NN) ? deg[i] : 0;
    int x = v;
    #pragma unroll
    for (int off = 1; off < 32; off <<= 1) {
        int y = __shfl_up_sync(0xffffffffu, x, off);
        if (lane >= off) x += y;
    }
    if (lane == 31) wsum[wid] = x;
    __syncthreads();
    if (wid == 0 && lane < 8) {
        int s = wsum[lane];
        #pragma unroll
        for (int off = 1; off < 8; off <<= 1) {
            int y = __shfl_up_sync(0xffu, s, off);
            if (lane >= off) s += y;
        }
        wsum[lane] = s;
    }
    __syncthreads();
    int excl = x - v + (wid ? wsum[wid - 1] : 0) + g_boff[blockIdx.x];
    if (i < NN) { g_rowptr[i] = excl; g_head[i] = excl; }
}

__global__ void k_fill(const int* __restrict__ src, const int* __restrict__ dst,
                       const float* __restrict__ dinv) {
    int e = blockIdx.x * blockDim.x + threadIdx.x;
    if (e >= EE) return;
    int s = src[e];
    int d = dst[e];
    float w = dinv[s] * dinv[d];
    int pos = atomicAdd(&g_head[d], 1);
    g_csr[pos] = ((unsigned long long)__float_as_uint(w) << 32) | (unsigned)s;
}

// ---------------------------------------------------------------------------
// Pre-transpose all 4 weights to fp16 [n][k]
// ---------------------------------------------------------------------------
__global__ void k_wth(const float* __restrict__ W0, const float* __restrict__ W1,
                      const float* __restrict__ W2, const float* __restrict__ W3) {
    const float* Ws[4] = {W0, W1, W2, W3};
    int i = blockIdx.x * 256 + threadIdx.x;   // 256 blocks -> 65536 elems
    int l = i >> 14;
    int r = i & 16383;
    int k = r >> 7;
    int n = r & 127;
    g_wth[l * HD * HD + n * HD + k] = __float2half(Ws[l][k * HD + n]);
}

// ---------------------------------------------------------------------------
// GEMM via mma.sync fp16 + ldmatrix fragments.
// CTA: 128 x 128, full K staged once. 8 warps = 4 row-groups x 2 col-halves;
// warp tile 32(M) x 64(N). Per k16 step: 2 LDSM.x4 (A) + 4 LDSM.x4 (B)
// + 16 HMMA. Pitch 136 halves (68 words): LDSM banks 4*row -> conflict-free.
// ---------------------------------------------------------------------------
__global__ __launch_bounds__(256, 2) void k_gemm_f16(
    const float* __restrict__ X, const __half* __restrict__ Wt,
    __half* __restrict__ XWH)
{
    extern __shared__ __half smh[];
    __half* Ah = smh;
    __half* Ws = smh + 128 * PH;

    const int tid = threadIdx.x;
    const int wid = tid >> 5;
    const int lane = tid & 31;
    const int g = lane >> 2;              // 0..7
    const int t4 = lane & 3;              // 0..3
    const int mr = wid & 3;               // row group: rows mr*32..+32
    const int nc = wid >> 2;              // col half:  cols nc*64..+64
    const int blockRow = blockIdx.x * 128;

    // ---- stage A: fp32 -> fp16 (hi only), STS.64 ----
    {
        int r = tid & 127;
        int hh = tid >> 7;                // k half: 0 or 1
        bool ok = (blockRow + r) < NN;
        const float* xr = X + (size_t)(blockRow + r) * HD + hh * 64;
        __half* ahp = Ah + r * PH + hh * 64;
        #pragma unroll
        for (int i = 0; i < 16; i++) {
            float4 v = ok ? *(const float4*)(xr + i * 4)
                          : make_float4(0.f, 0.f, 0.f, 0.f);
            H4U p;
            p.h[0] = __float22half2_rn(make_float2(v.x, v.y));
            p.h[1] = __float22half2_rn(make_float2(v.z, v.w));
            *(uint2*)(ahp + i * 4) = p.u;
        }
    }
    // ---- stage Wt rows (fp16 copy) ----
    #pragma unroll
    for (int i = 0; i < 8; i++) {
        int s = tid + i * 256;
        int n = s >> 4, kg = s & 15;
        *(uint4*)(Ws + n * PH + kg * 8) = *(const uint4*)(Wt + n * HD + kg * 8);
    }
    __syncthreads();

    // ---- ldmatrix lane-address bases (element offsets within Ah/Ws) ----
    // A tile (m16k16) at (r0, kb): addr = (r0 + (lane&15))*PH + kb + (lane>>4)*8
    // B x4 (2 n8 tiles) at (n0, kb): row = n0 + (lane&7) + (lane>>4)*8,
    //                                k  = kb + ((lane>>3)&1)*8
    const uint32_t AhB = smem_u32(Ah);
    const uint32_t WsB = smem_u32(Ws);
    const int aRow = mr * 32 + (lane & 15);
    const int aKof = (lane >> 4) * 8;
    const int bRowOf = (lane & 7) + (lane >> 4) * 8;
    const int bKof = ((lane >> 3) & 1) * 8;

    float acc[2][8][4] = {};

    #pragma unroll
    for (int ks = 0; ks < 8; ks++) {
        const int kb = ks * 16;
        uint32_t a[2][4];
        #pragma unroll
        for (int mt = 0; mt < 2; mt++) {
            uint32_t addr = AhB + ((aRow + mt * 16) * PH + kb + aKof) * 2;
            ldsm_x4(a[mt][0], a[mt][1], a[mt][2], a[mt][3], addr);
        }
        #pragma unroll
        for (int ng = 0; ng < 4; ng++) {
            int n0 = nc * 64 + ng * 16;
            uint32_t addr = WsB + ((n0 + bRowOf) * PH + kb + bKof) * 2;
            uint32_t b0a, b1a, b0b, b1b;
            ldsm_x4(b0a, b1a, b0b, b1b, addr);
            #pragma unroll
            for (int mt = 0; mt < 2; mt++) {
                mma_f16(acc[mt][ng * 2],     a[mt][0], a[mt][1], a[mt][2], a[mt][3], b0a, b1a);
                mma_f16(acc[mt][ng * 2 + 1], a[mt][0], a[mt][1], a[mt][2], a[mt][3], b0b, b1b);
            }
        }
    }

    // ---- epilogue: f32 acc -> half2 STG.32 ----
    #pragma unroll
    for (int mt = 0; mt < 2; mt++) {
        int orow = blockRow + mr * 32 + mt * 16 + g;
        #pragma unroll
        for (int nt = 0; nt < 8; nt++) {
            __half2 u0 = __float22half2_rn(make_float2(acc[mt][nt][0], acc[mt][nt][1]));
            __half2 u1 = __float22half2_rn(make_float2(acc[mt][nt][2], acc[mt][nt][3]));
            int col = nc * 64 + nt * 8 + t4 * 2;
            if (orow < NN)
                *(__half2*)(XWH + (size_t)orow * HD + col) = u0;
            if (orow + 8 < NN)
                *(__half2*)(XWH + (size_t)(orow + 8) * HD + col) = u1;
        }
    }
}

// ---------------------------------------------------------------------------
// CSR gather on fp16 XW + self-loop + bias + ELU fused. One warp per node;
// lane owns 4 cols = 8 bytes (uint2) per row. fp32 accumulation, MLP=2.
// ---------------------------------------------------------------------------
__global__ __launch_bounds__(256) void k_gather(
    const __half* __restrict__ XWH, const float* __restrict__ dinv,
    const float* __restrict__ bias, float* __restrict__ H)
{
    int gt   = blockIdx.x * blockDim.x + threadIdx.x;
    int node = gt >> 5;
    int lane = gt & 31;
    if (node >= NN) return;

    int beg = g_rowptr[node];
    int end = g_rowptr[node + 1];
    float d  = dinv[node];
    float d2 = d * d;

    H4U sl; sl.u = *(const uint2*)(XWH + (size_t)node * HD + lane * 4);
    float2 s0 = __half22float2(sl.h[0]);
    float2 s1 = __half22float2(sl.h[1]);
    float4 acc  = make_float4(s0.x * d2, s0.y * d2, s1.x * d2, s1.y * d2);
    float4 acc1 = make_float4(0.f, 0.f, 0.f, 0.f);

    int j = beg;
    for (; j + 1 < end; j += 2) {
        unsigned long long pv0 = g_csr[j];
        unsigned long long pv1 = g_csr[j + 1];
        int   sA = (int)(unsigned)(pv0 & 0xffffffffu);
        int   sB = (int)(unsigned)(pv1 & 0xffffffffu);
        float w0 = __uint_as_float((unsigned)(pv0 >> 32));
        float w1 = __uint_as_float((unsigned)(pv1 >> 32));
        H4U r0; r0.u = *(const uint2*)(XWH + (size_t)sA * HD + lane * 4);
        H4U r1; r1.u = *(const uint2*)(XWH + (size_t)sB * HD + lane * 4);
        float2 a = __half22float2(r0.h[0]);
        float2 b = __half22float2(r0.h[1]);
        float2 c = __half22float2(r1.h[0]);
        float2 e = __half22float2(r1.h[1]);
        acc.x  = fmaf(w0, a.x, acc.x);
        acc.y  = fmaf(w0, a.y, acc.y);
        acc.z  = fmaf(w0, b.x, acc.z);
        acc.w  = fmaf(w0, b.y, acc.w);
        acc1.x = fmaf(w1, c.x, acc1.x);
        acc1.y = fmaf(w1, c.y, acc1.y);
        acc1.z = fmaf(w1, e.x, acc1.z);
        acc1.w = fmaf(w1, e.y, acc1.w);
    }
    if (j < end) {
        unsigned long long pv = g_csr[j];
        int   s = (int)(unsigned)(pv & 0xffffffffu);
        float w = __uint_as_float((unsigned)(pv >> 32));
        H4U r0; r0.u = *(const uint2*)(XWH + (size_t)s * HD + lane * 4);
        float2 a = __half22float2(r0.h[0]);
        float2 b = __half22float2(r0.h[1]);
        acc.x = fmaf(w, a.x, acc.x);
        acc.y = fmaf(w, a.y, acc.y);
        acc.z = fmaf(w, b.x, acc.z);
        acc.w = fmaf(w, b.y, acc.w);
    }
    acc.x += acc1.x; acc.y += acc1.y; acc.z += acc1.z; acc.w += acc1.w;

    float4 bb = *(const float4*)(bias + lane * 4);
    float4 r;
    r.x = elu(acc.x + bb.x);
    r.y = elu(acc.y + bb.y);
    r.z = elu(acc.z + bb.z);
    r.w = elu(acc.w + bb.w);
    *(float4*)(H + (size_t)node * HD + lane * 4) = r;
}

// ---------------------------------------------------------------------------
// Output head: S = elu(h @ Wm2 + bm2) (N x 10). Warp per row.
// (Wm1/bm1 are dead code in the reference.)
// ---------------------------------------------------------------------------
__global__ __launch_bounds__(256) void k_mlp(
    const float* __restrict__ Hin, const float* __restrict__ Wm,
    const float* __restrict__ bm, float* __restrict__ S)
{
    __shared__ float Ws[HD * 10];
    __shared__ float bs[10];
    int tid = threadIdx.x;
    for (int i = tid; i < HD * 10; i += 256) Ws[i] = Wm[i];
    if (tid < 10) bs[tid] = bm[tid];
    __syncthreads();

    int warp = tid >> 5, lane = tid & 31;
    int row = blockIdx.x * 8 + warp;
    if (row >= NN) return;

    float acc[10] = {};
    #pragma unroll
    for (int kk = 0; kk < 4; kk++) {
        int k = kk * 32 + lane;
        float hv = Hin[(size_t)row * HD + k];
        #pragma unroll
        for (int c = 0; c < 10; c++) acc[c] += hv * Ws[k * 10 + c];
    }
    #pragma unroll
    for (int c = 0; c < 10; c++) {
        #pragma unroll
        for (int off = 16; off; off >>= 1)
            acc[c] += __shfl_down_sync(0xffffffffu, acc[c], off);
    }
    if (lane == 0) {
        #pragma unroll
        for (int c = 0; c < 10; c++) {
            float v = acc[c] + bs[c];
            S[(size_t)row * 10 + c] = elu(v);
        }
    }
}

// ---------------------------------------------------------------------------
extern "C" void kernel_launch(void* const* d_in, const int* in_sizes, int n_in,
                              void* d_out, int out_size)
{
    const float* x   = (const float*)d_in[0];
    const int*   ei  = (const int*)d_in[1];
    const int*   src = ei;
    const int*   dst = ei + EE;
    const float* W[4] = {(const float*)d_in[2], (const float*)d_in[4],
                         (const float*)d_in[6], (const float*)d_in[8]};
    const float* b[4] = {(const float*)d_in[3], (const float*)d_in[5],
                         (const float*)d_in[7], (const float*)d_in[9]};
    const float* Wm2 = (const float*)d_in[12];
    const float* bm2 = (const float*)d_in[13];

    float* out_h = (float*)d_out;                 // [NN, 128]
    float* out_S = out_h + (size_t)NN * HD;       // [NN, 10]

    __half *xwh, *wth;
    float *h1, *h2, *dinv;
    int* deg;
    cudaGetSymbolAddress((void**)&xwh,  g_xwh);
    cudaGetSymbolAddress((void**)&wth,  g_wth);
    cudaGetSymbolAddress((void**)&h1,   g_h1);
    cudaGetSymbolAddress((void**)&h2,   g_h2);
    cudaGetSymbolAddress((void**)&dinv, g_dinv);
    cudaGetSymbolAddress((void**)&deg,  g_deg);

    cudaFuncSetAttribute(k_gemm_f16,
                         cudaFuncAttributeMaxDynamicSharedMemorySize,
                         GEMM_SMEM);

    const int gather_blocks = (NN * 32 + 255) / 256;      // 6250

    // Launch order keeps gemm_l0 at index 3 (ncu capture window).
    k_zero_deg<<<(NN + 255) / 256, 256>>>(deg);           // 0
    k_hist<<<(EE + 255) / 256, 256>>>(dst, deg);          // 1
    k_wth<<<256, 256>>>(W[0], W[1], W[2], W[3]);          // 2
    k_gemm_f16<<<MB_TILES, 256, GEMM_SMEM>>>(x, wth, xwh);  // 3 (captured)
    k_blockred<<<SCAN_BLOCKS, 256>>>(deg, dinv);          // 4
    k_scansums<<<1, 256>>>();                             // 5
    k_scanfinal<<<SCAN_BLOCKS, 256>>>(deg);               // 6
    k_fill<<<(EE + 255) / 256, 256>>>(src, dst, dinv);    // 7
    k_gather<<<gather_blocks, 256>>>(xwh, dinv, b[0], h1);  // 8

    const float* in = h1;
    float* houts[4] = {h1, h2, h1, out_h};
    for (int l = 1; l < 4; l++) {
        k_gemm_f16<<<MB_TILES, 256, GEMM_SMEM>>>(in, wth + (size_t)l * HD * HD, xwh);
        k_gather<<<gather_blocks, 256>>>(xwh, dinv, b[l], houts[l]);
        in = houts[l];
    }

    k_mlp<<<(NN + 7) / 8, 256>>>(out_h, Wm2, bm2, out_S);
}